// round 5
// baseline (speedup 1.0000x reference)
#include <cuda_runtime.h>
#include <cstdint>
#include <math_constants.h>

#define DCOLS 2048
#define THREADS 256
#define CAP 256
#define GRID 888          // 148 SMs * 6 resident CTAs -> single persistent wave
#define ROW_BYTES 8192
#define STAGE_BYTES 16384 // x row + mask row

// ---------- PTX helpers ----------
__device__ __forceinline__ uint32_t s2u(const void* p) {
    uint32_t a;
    asm("{ .reg .u64 t; cvta.to.shared.u64 t, %1; cvt.u32.u64 %0, t; }"
        : "=r"(a) : "l"(p));
    return a;
}
__device__ __forceinline__ void mbar_init(uint32_t mbar, uint32_t cnt) {
    asm volatile("mbarrier.init.shared::cta.b64 [%0], %1;" :: "r"(mbar), "r"(cnt) : "memory");
}
__device__ __forceinline__ void mbar_expect_tx(uint32_t mbar, uint32_t bytes) {
    asm volatile("mbarrier.arrive.expect_tx.shared::cta.b64 _, [%0], %1;"
                 :: "r"(mbar), "r"(bytes) : "memory");
}
__device__ __forceinline__ void mbar_wait(uint32_t mbar, uint32_t phase) {
    asm volatile(
        "{\n\t.reg .pred P;\n\t"
        "WAIT_%=:\n\t"
        "mbarrier.try_wait.parity.acquire.cta.shared::cta.b64 P, [%0], %1, 0x989680;\n\t"
        "@!P bra WAIT_%=;\n\t}"
        :: "r"(mbar), "r"(phase) : "memory");
}
__device__ __forceinline__ void bulk_ld(uint32_t smem_dst, const void* gmem_src,
                                        uint32_t bytes, uint32_t mbar) {
    asm volatile(
        "cp.async.bulk.shared::cta.global.mbarrier::complete_tx::bytes [%0], [%1], %2, [%3];"
        :: "r"(smem_dst), "l"(gmem_src), "r"(bytes), "r"(mbar) : "memory");
}
__device__ __forceinline__ void bulk_st(void* gmem_dst, uint32_t smem_src, uint32_t bytes) {
    asm volatile("cp.async.bulk.global.shared::cta.bulk_group [%0], [%1], %2;"
                 :: "l"(gmem_dst), "r"(smem_src), "r"(bytes) : "memory");
}
__device__ __forceinline__ void bulk_commit() {
    asm volatile("cp.async.bulk.commit_group;" ::: "memory");
}
__device__ __forceinline__ void bulk_wait0() {
    asm volatile("cp.async.bulk.wait_group 0;" ::: "memory");
}
__device__ __forceinline__ void fence_async() {
    asm volatile("fence.proxy.async.shared::cta;" ::: "memory");
}

// ---------- exact threshold solvers ----------
__device__ __forceinline__ float michelot_list(const float* c, int k) {
    float S = 0.f;
    for (int i = 0; i < k; i++) S += c[i];
    float tau = (S - 1.0f) / (float)k;
    int prevc = k;
    for (int it = 0; it < CAP + 2; it++) {
        float s = 0.f; int cc = 0;
        for (int i = 0; i < k; i++) {
            float z = c[i];
            if (z > tau) { s += z; cc++; }
        }
        if (cc == prevc || cc == 0) break;
        tau = (s - 1.0f) / (float)cc;
        prevc = cc;
    }
    return tau;
}
__device__ float michelot_row_smem(const float* xr, const int* mr) {
    // Fallback (statistically unreachable): serial Michelot over full smem row.
    float S = 0.f; int k = 0;
    for (int i = 0; i < DCOLS; i++) if (mr[i]) { S += xr[i]; k++; }
    float tau = (S - 1.0f) / (float)k;
    int prevc = k;
    for (int it = 0; it < DCOLS + 2; it++) {
        float s = 0.f; int cc = 0;
        for (int i = 0; i < DCOLS; i++) {
            if (mr[i]) { float z = xr[i]; if (z > tau) { s += z; cc++; } }
        }
        if (cc == prevc || cc == 0) break;
        tau = (s - 1.0f) / (float)cc;
        prevc = cc;
    }
    return tau;
}

__global__ __launch_bounds__(THREADS, 6) void sparsemax_kernel(
    const float* __restrict__ x,
    const int* __restrict__ mask,
    float* __restrict__ out,
    int rows)
{
    __shared__ alignas(128) float sx[2][DCOLS];   // 16 KB (also reused as output stage)
    __shared__ alignas(128) int   smk[2][DCOLS];  // 16 KB
    __shared__ float s_red[8];
    __shared__ int   s_redi[8];
    __shared__ int   s_cnt;
    __shared__ float s_tau;
    __shared__ float s_cand[CAP];
    __shared__ alignas(8) uint64_t mbar_mem[2];

    const int t = threadIdx.x;
    const int warp = t >> 5, lane = t & 31;
    const uint32_t mb[2] = { s2u(&mbar_mem[0]), s2u(&mbar_mem[1]) };
    const uint32_t sx_u[2] = { s2u(&sx[0][0]), s2u(&sx[1][0]) };
    const uint32_t sm_u[2] = { s2u(&smk[0][0]), s2u(&smk[1][0]) };

    if (t == 0) {
        mbar_init(mb[0], 1);
        mbar_init(mb[1], 1);
        fence_async();
    }
    __syncthreads();

    int row = blockIdx.x;

    // ---- prologue: kick off loads for first two rows ----
    if (t == 0) {
        if (row < rows) {
            mbar_expect_tx(mb[0], STAGE_BYTES);
            bulk_ld(sx_u[0], x    + (size_t)row * DCOLS, ROW_BYTES, mb[0]);
            bulk_ld(sm_u[0], mask + (size_t)row * DCOLS, ROW_BYTES, mb[0]);
        }
        int r1 = row + GRID;
        if (r1 < rows) {
            mbar_expect_tx(mb[1], STAGE_BYTES);
            bulk_ld(sx_u[1], x    + (size_t)r1 * DCOLS, ROW_BYTES, mb[1]);
            bulk_ld(sm_u[1], mask + (size_t)r1 * DCOLS, ROW_BYTES, mb[1]);
        }
    }

    uint32_t ph[2] = {0u, 0u};
    int s = 0;

    while (row < rows) {
        // ---- wait for stage data (TMA complete_tx, acquire) ----
        mbar_wait(mb[s], ph[s]);
        ph[s] ^= 1u;

        const float4* xr = reinterpret_cast<const float4*>(sx[s]);
        const int4*   mr = reinterpret_cast<const int4*>(smk[s]);
        float4 v0 = xr[t];
        float4 v1 = xr[t + THREADS];
        int4 m0 = mr[t];
        int4 m1 = mr[t + THREADS];

        float vals[8] = {v0.x, v0.y, v0.z, v0.w, v1.x, v1.y, v1.z, v1.w};
        bool  act[8]  = {m0.x != 0, m0.y != 0, m0.z != 0, m0.w != 0,
                         m1.x != 0, m1.y != 0, m1.z != 0, m1.w != 0};

        // ---- phase 1: block reduce max / count ----
        float mx = -CUDART_INF_F;
        int cnt = 0;
        #pragma unroll
        for (int i = 0; i < 8; i++) if (act[i]) { mx = fmaxf(mx, vals[i]); cnt++; }
        #pragma unroll
        for (int o = 16; o; o >>= 1) {
            mx = fmaxf(mx, __shfl_xor_sync(0xFFFFFFFFu, mx, o));
            cnt += __shfl_xor_sync(0xFFFFFFFFu, cnt, o);
        }
        if (lane == 0) { s_red[warp] = mx; s_redi[warp] = cnt; }
        if (t == 0) s_cnt = 0;
        __syncthreads();                                  // sync A
        float allmax = -CUDART_INF_F; int allcnt = 0;
        #pragma unroll
        for (int i = 0; i < 8; i++) { allmax = fmaxf(allmax, s_red[i]); allcnt += s_redi[i]; }

        float tau;
        if (allcnt != 0) {                                // uniform branch
            // ---- phase 2: compact candidates {active & x > max-1} ----
            const float thresh = allmax - 1.0f;
            #pragma unroll
            for (int i = 0; i < 8; i++) {
                if (act[i] && vals[i] > thresh) {
                    int idx = atomicAdd(&s_cnt, 1);
                    if (idx < CAP) s_cand[idx] = vals[i];
                }
            }
            __syncthreads();                              // sync B
            const int k = s_cnt;
            // ---- phase 3: exact threshold ----
            if (t == 0) {
                s_tau = (k <= CAP) ? michelot_list(s_cand, k)
                                   : michelot_row_smem(sx[s], smk[s]);
            }
            __syncthreads();                              // sync C
            tau = s_tau;
        } else {
            tau = CUDART_INF_F;                           // all-zero row
        }

        // ---- phase 4: write p in place into the x stage buffer ----
        float4* ox = reinterpret_cast<float4*>(sx[s]);
        float4 o0, o1;
        o0.x = act[0] ? fmaxf(vals[0] - tau, 0.f) : 0.f;
        o0.y = act[1] ? fmaxf(vals[1] - tau, 0.f) : 0.f;
        o0.z = act[2] ? fmaxf(vals[2] - tau, 0.f) : 0.f;
        o0.w = act[3] ? fmaxf(vals[3] - tau, 0.f) : 0.f;
        o1.x = act[4] ? fmaxf(vals[4] - tau, 0.f) : 0.f;
        o1.y = act[5] ? fmaxf(vals[5] - tau, 0.f) : 0.f;
        o1.z = act[6] ? fmaxf(vals[6] - tau, 0.f) : 0.f;
        o1.w = act[7] ? fmaxf(vals[7] - tau, 0.f) : 0.f;
        ox[t] = o0;
        ox[t + THREADS] = o1;
        __syncthreads();                                  // sync D: all p visible

        // ---- phase 5: async bulk store + refill this stage ----
        if (t == 0) {
            fence_async();                                // generic STS -> async proxy
            bulk_st(out + (size_t)row * DCOLS, sx_u[s], ROW_BYTES);
            bulk_commit();
            bulk_wait0();                                 // stage s store drained
            int r2 = row + 2 * GRID;
            if (r2 < rows) {
                mbar_expect_tx(mb[s], STAGE_BYTES);
                bulk_ld(sx_u[s], x    + (size_t)r2 * DCOLS, ROW_BYTES, mb[s]);
                bulk_ld(sm_u[s], mask + (size_t)r2 * DCOLS, ROW_BYTES, mb[s]);
            }
        }
        row += GRID;
        s ^= 1;
    }
}

extern "C" void kernel_launch(void* const* d_in, const int* in_sizes, int n_in,
                              void* d_out, int out_size) {
    const float* x = (const float*)d_in[0];
    const int* mask = (const int*)d_in[1];
    float* out = (float*)d_out;

    const int rows = out_size / DCOLS;   // 16384
    sparsemax_kernel<<<GRID, THREADS>>>(x, mask, out, rows);
}

// round 6
// speedup vs baseline: 1.1826x; 1.1826x over previous
#include <cuda_runtime.h>
#include <cstdint>
#include <math_constants.h>

#define DCOLS 2048
#define THREADS 256
#define CAP 256

__device__ __forceinline__ float michelot_list(const float* c, int k) {
    // Exact sparsemax threshold over candidate list c[0..k) (all finite, > max-1).
    float S = 0.f;
    for (int i = 0; i < k; i++) S += c[i];
    float tau = (S - 1.0f) / (float)k;
    int prevc = k;
    for (int it = 0; it < CAP + 2; it++) {
        float s = 0.f; int cc = 0;
        for (int i = 0; i < k; i++) {
            float z = c[i];
            if (z > tau) { s += z; cc++; }
        }
        if (cc == prevc || cc == 0) break;
        tau = (s - 1.0f) / (float)cc;
        prevc = cc;
    }
    return tau;
}

__device__ float michelot_row_global(const float* xr, const int* mr) {
    // Fallback (statistically unreachable): serial Michelot over full row.
    float S = 0.f; int k = 0;
    for (int i = 0; i < DCOLS; i++) if (mr[i]) { S += xr[i]; k++; }
    float tau = (S - 1.0f) / (float)k;
    int prevc = k;
    for (int it = 0; it < DCOLS + 2; it++) {
        float s = 0.f; int cc = 0;
        for (int i = 0; i < DCOLS; i++) {
            if (mr[i]) { float z = xr[i]; if (z > tau) { s += z; cc++; } }
        }
        if (cc == prevc || cc == 0) break;
        tau = (s - 1.0f) / (float)cc;
        prevc = cc;
    }
    return tau;
}

__global__ __launch_bounds__(THREADS, 8) void sparsemax_kernel(
    const float* __restrict__ x,
    const int* __restrict__ mask,
    float* __restrict__ out)
{
    const int row = blockIdx.x;
    const int t = threadIdx.x;
    const int warp = t >> 5, lane = t & 31;

    const float4* xr = reinterpret_cast<const float4*>(x + (size_t)row * DCOLS);
    const int4*   mr = reinterpret_cast<const int4*>(mask + (size_t)row * DCOLS);
    float4* orow = reinterpret_cast<float4*>(out + (size_t)row * DCOLS);

    __shared__ float s_wmax[8];
    __shared__ int   s_cnt;
    __shared__ float s_tau;
    __shared__ float s_cand[CAP];

    // Load 8 values + 8 mask words, fold mask immediately: inactive -> -inf.
    float4 v0 = xr[t];
    float4 v1 = xr[t + THREADS];
    int4 m0 = mr[t];
    int4 m1 = mr[t + THREADS];

    float vals[8];
    vals[0] = m0.x ? v0.x : -CUDART_INF_F;
    vals[1] = m0.y ? v0.y : -CUDART_INF_F;
    vals[2] = m0.z ? v0.z : -CUDART_INF_F;
    vals[3] = m0.w ? v0.w : -CUDART_INF_F;
    vals[4] = m1.x ? v1.x : -CUDART_INF_F;
    vals[5] = m1.y ? v1.y : -CUDART_INF_F;
    vals[6] = m1.z ? v1.z : -CUDART_INF_F;
    vals[7] = m1.w ? v1.w : -CUDART_INF_F;

    // ---- Phase 1: block max (max alone decides: max is always a candidate) ----
    float mx = vals[0];
    #pragma unroll
    for (int i = 1; i < 8; i++) mx = fmaxf(mx, vals[i]);
    #pragma unroll
    for (int o = 16; o; o >>= 1)
        mx = fmaxf(mx, __shfl_xor_sync(0xFFFFFFFFu, mx, o));
    if (lane == 0) s_wmax[warp] = mx;
    if (t == 0) s_cnt = 0;
    __syncthreads();
    float allmax = s_wmax[0];
    #pragma unroll
    for (int i = 1; i < 8; i++) allmax = fmaxf(allmax, s_wmax[i]);

    // ---- Phase 2: warp-aggregated compaction of {v > max-1} ----
    // (if row is all-inactive: allmax=-inf, thresh=-inf, -inf > -inf false -> k=0)
    const float thresh = allmax - 1.0f;
    #pragma unroll
    for (int i = 0; i < 8; i++) {
        const bool p = vals[i] > thresh;
        const unsigned b = __ballot_sync(0xFFFFFFFFu, p);
        if (b) {
            const int leader = __ffs(b) - 1;
            int base = 0;
            if (lane == leader) base = atomicAdd(&s_cnt, __popc(b));
            base = __shfl_sync(0xFFFFFFFFu, base, leader);
            if (p) {
                int idx = base + __popc(b & ((1u << lane) - 1u));
                if (idx < CAP) s_cand[idx] = vals[i];
            }
        }
    }
    __syncthreads();
    const int k = s_cnt;

    // ---- Phase 3: exact threshold (serial, tiny candidate set) ----
    if (t == 0) {
        float tau;
        if (k == 0)        tau = CUDART_INF_F;            // all-inactive row -> zeros
        else if (k <= CAP) tau = michelot_list(s_cand, k);
        else               tau = michelot_row_global(x + (size_t)row * DCOLS,
                                                     mask + (size_t)row * DCOLS);
        s_tau = tau;
    }
    __syncthreads();
    const float tau = s_tau;

    // ---- Phase 4: p = relu(v - tau); -inf entries give 0 automatically ----
    float4 o0, o1;
    o0.x = fmaxf(vals[0] - tau, 0.f);
    o0.y = fmaxf(vals[1] - tau, 0.f);
    o0.z = fmaxf(vals[2] - tau, 0.f);
    o0.w = fmaxf(vals[3] - tau, 0.f);
    o1.x = fmaxf(vals[4] - tau, 0.f);
    o1.y = fmaxf(vals[5] - tau, 0.f);
    o1.z = fmaxf(vals[6] - tau, 0.f);
    o1.w = fmaxf(vals[7] - tau, 0.f);
    orow[t] = o0;
    orow[t + THREADS] = o1;
}

extern "C" void kernel_launch(void* const* d_in, const int* in_sizes, int n_in,
                              void* d_out, int out_size) {
    const float* x = (const float*)d_in[0];
    const int* mask = (const int*)d_in[1];
    float* out = (float*)d_out;

    const int rows = out_size / DCOLS;   // 16384
    sparsemax_kernel<<<rows, THREADS>>>(x, mask, out);
}